// round 16
// baseline (speedup 1.0000x reference)
#include <cuda_runtime.h>
#include <cuda_bf16.h>
#include <cstdint>

#define G_N   2048
#define HID   128
#define NMAX  100000
#define EMAX  600000

// ---------------- scratch (static device globals; no allocations) -------------
static __device__ __align__(16) int   d_deg[NMAX];
static __device__ __align__(16) int   d_rowptr[NMAX + 1];
static __device__ __align__(16) int   d_woff[NMAX];
static __device__ __align__(16) int   d_csrsrc[EMAX];
static __device__ __align__(16) int   d_gstart[G_N + 1];
static __device__ __align__(16) int   d_ctr[4];
static __device__ __align__(16) float d_z8[(size_t)NMAX * 8];
static __device__ __align__(16) float d_h1[(size_t)NMAX * HID];
static __device__ __align__(16) float d_h2[(size_t)NMAX * HID];
static __device__ __align__(16) float d_zbuf[(size_t)NMAX * HID];
static __device__ __align__(16) float d_pooled[(size_t)G_N * 384];
static __device__ __align__(16) float d_grow[(size_t)G_N * HID];
static __device__ __align__(16) float d_zc[(size_t)G_N * HID];
static __device__ __align__(16) float d_mu[HID];
static __device__ __align__(16) float d_rstd[HID];

// ---------------- CSR build ---------------------------------------------------
// merged: clear degree + steal counters + pooled accumulator + graph starts
__global__ void k_clear_gstart(const int* __restrict__ batch, int N) {
    int n = blockIdx.x * blockDim.x + threadIdx.x;
    int nth = gridDim.x * blockDim.x;
    if (n < 4) d_ctr[n] = 0;
    for (int i = n; i < G_N * 384; i += nth) d_pooled[i] = 0.f;
    if (n >= N) return;
    d_deg[n] = 0;
    int b = batch[n];
    int bp = (n == 0) ? -1 : batch[n - 1];
    for (int g = bp + 1; g <= b; g++) d_gstart[g] = n;
    if (n == N - 1)
        for (int g = b + 1; g <= G_N; g++) d_gstart[g] = N;
}

__global__ void k_hist(const int* __restrict__ dst, int E) {
    int i = blockIdx.x * blockDim.x + threadIdx.x;
    if (i < E) atomicAdd(&d_deg[dst[i]], 1);
}

__global__ void k_scan(int N, int E) {
    __shared__ int part[1024];
    int tid = threadIdx.x;
    int chunk = (N + 1023) / 1024;
    int beg = tid * chunk;
    int end = min(beg + chunk, N);
    int s = 0;
    for (int i = beg; i < end; i++) s += d_deg[i];
    part[tid] = s;
    __syncthreads();
    for (int off = 1; off < 1024; off <<= 1) {
        int v = (tid >= off) ? part[tid - off] : 0;
        __syncthreads();
        part[tid] += v;
        __syncthreads();
    }
    int run = (tid == 0) ? 0 : part[tid - 1];
    for (int i = beg; i < end; i++) {
        d_rowptr[i] = run;
        d_woff[i] = run;
        run += d_deg[i];
    }
    if (tid == 1023) d_rowptr[N] = E;
}

__global__ void k_fill(const int* __restrict__ src, const int* __restrict__ dst, int E) {
    int i = blockIdx.x * blockDim.x + threadIdx.x;
    if (i < E) {
        int p = atomicAdd(&d_woff[dst[i]], 1);
        d_csrsrc[p] = src[i];
    }
}

// ---------------- aggregation (high-TLP standalone kernels) --------------------
__global__ void k_agg7(const float* __restrict__ x, int N) {
    int n = blockIdx.x * blockDim.x + threadIdx.x;
    if (n >= N) return;
    float a[8];
#pragma unroll
    for (int j = 0; j < 7; j++) a[j] = x[n * 7 + j];
    a[7] = 0.f;
    int b = d_rowptr[n], e = d_rowptr[n + 1];
    for (int i = b; i < e; i++) {
        int s = d_csrsrc[i];
#pragma unroll
        for (int j = 0; j < 7; j++) a[j] += x[s * 7 + j];
    }
#pragma unroll
    for (int j = 0; j < 8; j++) d_z8[(size_t)n * 8 + j] = a[j];
}

__global__ void k_agg128(const float* __restrict__ h, float* __restrict__ z, int N) {
    int w = (blockIdx.x * blockDim.x + threadIdx.x) >> 5;
    int lane = threadIdx.x & 31;
    if (w >= N) return;
    const float4* hv = (const float4*)h;
    float4 acc = hv[(size_t)w * 32 + lane];
    int b = d_rowptr[w], e = d_rowptr[w + 1];
    for (int i = b; i < e; i++) {
        int s = d_csrsrc[i];
        float4 v = hv[(size_t)s * 32 + lane];
        acc.x += v.x; acc.y += v.y; acc.z += v.z; acc.w += v.w;
    }
    ((float4*)z)[(size_t)w * 32 + lane] = acc;
}

// ============ bf16 3-term emulated-fp32 fused 2-layer MLP + pooled epilogue ====
// out = relu( relu(A @ W1 + b1) @ W2 + b2 ); per-tile per-graph column sums are
// atomically accumulated into pooled[] (global_add_pool fused — rows sorted by
// graph). out == nullptr skips the gmem store (conv3: h3 has no other consumer).
// Each fp32 operand x = hi(bf16) + lo(bf16); D = Ah@Wh + Ah@Wl + Al@Wh.
// mma.sync.m16n8k16 bf16; 256 threads (8 warps, 4x2), tile M=128 x N=128.
// Persistent CTAs + work-stealing tile scheduler (d_ctr reset each replay).

#define PT 68                                   // pitch in 32-bit words
#define TILE_W (128 * PT * 4)                   // 34816 bytes per bf16 tile
#define SM_AH  0
#define SM_AL  (TILE_W)
#define SM_W1H (2 * TILE_W)
#define SM_W1L (3 * TILE_W)
#define SM_W2H (4 * TILE_W)
#define SM_W2L (5 * TILE_W)
#define MMA_SMEM (6 * TILE_W)                   // 208896 bytes
#define PST 132                                 // fp32 staging pitch (reuses AH+AL)

__device__ __forceinline__ void mma16(float* c, const uint32_t* a, const uint32_t* b) {
    asm volatile(
        "mma.sync.aligned.m16n8k16.row.col.f32.bf16.bf16.f32 "
        "{%0,%1,%2,%3}, {%4,%5,%6,%7}, {%8,%9}, {%0,%1,%2,%3};"
        : "+f"(c[0]), "+f"(c[1]), "+f"(c[2]), "+f"(c[3])
        : "r"(a[0]), "r"(a[1]), "r"(a[2]), "r"(a[3]), "r"(b[0]), "r"(b[1]));
}

__device__ __forceinline__ void split2(float x0, float x1, uint32_t& h, uint32_t& l) {
    __nv_bfloat16 h0 = __float2bfloat16_rn(x0);
    __nv_bfloat16 h1 = __float2bfloat16_rn(x1);
    float r0 = x0 - __bfloat162float(h0);
    float r1 = x1 - __bfloat162float(h1);
    __nv_bfloat16 l0 = __float2bfloat16_rn(r0);
    __nv_bfloat16 l1 = __float2bfloat16_rn(r1);
    h = (uint32_t)__bfloat16_as_ushort(h0) | ((uint32_t)__bfloat16_as_ushort(h1) << 16);
    l = (uint32_t)__bfloat16_as_ushort(l0) | ((uint32_t)__bfloat16_as_ushort(l1) << 16);
}

__device__ __forceinline__ void gemm3(const uint32_t* sAh, const uint32_t* sAl,
                                      const uint32_t* sWh, const uint32_t* sWl,
                                      int nks, int r0, int n0, int g, int t,
                                      float acc[2][8][4]) {
    for (int ks = 0; ks < nks; ks++) {
        int kp0 = ks * 8;
        uint32_t ah[2][4], al[2][4];
#pragma unroll
        for (int mt = 0; mt < 2; mt++) {
            int rb = (r0 + mt * 16 + g) * PT + kp0 + t;
            ah[mt][0] = sAh[rb];              al[mt][0] = sAl[rb];
            ah[mt][1] = sAh[rb + 8 * PT];     al[mt][1] = sAl[rb + 8 * PT];
            ah[mt][2] = sAh[rb + 4];          al[mt][2] = sAl[rb + 4];
            ah[mt][3] = sAh[rb + 8 * PT + 4]; al[mt][3] = sAl[rb + 8 * PT + 4];
        }
#pragma unroll
        for (int nt = 0; nt < 8; nt++) {
            int wb = (n0 + nt * 8 + g) * PT + kp0 + t;
            uint32_t bh[2] = { sWh[wb], sWh[wb + 4] };
            uint32_t bl[2] = { sWl[wb], sWl[wb + 4] };
#pragma unroll
            for (int mt = 0; mt < 2; mt++) {
                mma16(acc[mt][nt], ah[mt], bh);
                mma16(acc[mt][nt], ah[mt], bl);
                mma16(acc[mt][nt], al[mt], bh);
            }
        }
    }
}

// mode 0: A = d_z8 [N,8] (7 real cols; kpairs 4..7 zeroed each tile), nks1 = 1
// mode 1: A = zbuf [N,128] float4-aligned, nks1 = 8
__global__ __launch_bounds__(256, 1)
void k_mma_mlp(const float* __restrict__ A, int mode, int N, int nks1, int cid,
               const float* __restrict__ W1, int kw1,
               const float* __restrict__ b1,
               const float* __restrict__ W2,
               const float* __restrict__ b2,
               float* __restrict__ out,
               const int* __restrict__ batch,
               float* __restrict__ pooled) {
    extern __shared__ char dsm[];
    uint32_t* sAh  = (uint32_t*)(dsm + SM_AH);
    uint32_t* sAl  = (uint32_t*)(dsm + SM_AL);
    uint32_t* sW1h = (uint32_t*)(dsm + SM_W1H);
    uint32_t* sW1l = (uint32_t*)(dsm + SM_W1L);
    uint32_t* sW2h = (uint32_t*)(dsm + SM_W2H);
    uint32_t* sW2l = (uint32_t*)(dsm + SM_W2L);
    float*    sStage = (float*)(dsm + SM_AH);   // fp32 staging reuses AH+AL
    __shared__ float sb1[128], sb2[128];
    __shared__ int sBatch[128];
    __shared__ int s_tile;

    int tid = threadIdx.x;
    int wid = tid >> 5, lane = tid & 31;
    int g = lane >> 2, t = lane & 3;
    int wr = wid & 3, wc = wid >> 2;
    int r0 = wr * 32;
    int n0 = wc * 64;

    if (tid < 128) { sb1[tid] = b1[tid]; sb2[tid] = b2[tid]; }

    // W1 -> transposed [n][kpair] hi/lo, zero-pad k >= kw1
    int kpw1 = nks1 * 8;
    for (int idx = tid; idx < 128 * kpw1; idx += 256) {
        int n = idx & 127, p = idx >> 7;
        int k0 = 2 * p, k1 = 2 * p + 1;
        float w0 = (k0 < kw1) ? W1[k0 * HID + n] : 0.f;
        float w1 = (k1 < kw1) ? W1[k1 * HID + n] : 0.f;
        uint32_t h, l;
        split2(w0, w1, h, l);
        sW1h[n * PT + p] = h;
        sW1l[n * PT + p] = l;
    }
    // W2 -> transposed [n][kpair] hi/lo
    for (int idx = tid; idx < 8192; idx += 256) {
        int n = idx & 127, p = idx >> 7;
        float w0 = W2[(2 * p) * HID + n];
        float w1 = W2[(2 * p + 1) * HID + n];
        uint32_t h, l;
        split2(w0, w1, h, l);
        sW2h[n * PT + p] = h;
        sW2l[n * PT + p] = l;
    }
    __syncthreads();

    int ntiles = (N + 127) >> 7;
    float acc[2][8][4];

    int tile = blockIdx.x;
    while (tile < ntiles) {
        int m0 = tile << 7;

        // ---- A-tile load -> bf16 hi/lo kpair words (+ batch slice) ----
        if (tid < 128) {
            int n = m0 + tid;
            sBatch[tid] = (n < N) ? batch[n] : -1;
        }
        if (mode == 1) {
            const float4* av = (const float4*)A;
            for (int idx = tid; idx < 4096; idx += 256) {
                int r = idx >> 5, seg = idx & 31;
                int n = m0 + r;
                float4 f = make_float4(0.f, 0.f, 0.f, 0.f);
                if (n < N) f = av[(size_t)n * 32 + seg];
                uint32_t h, l;
                split2(f.x, f.y, h, l);
                sAh[r * PT + 2 * seg] = h;     sAl[r * PT + 2 * seg] = l;
                split2(f.z, f.w, h, l);
                sAh[r * PT + 2 * seg + 1] = h; sAl[r * PT + 2 * seg + 1] = l;
            }
        } else {
            // d_z8: 2 float4/row (kpairs 0..3); kpairs 4..7 MUST be zeroed each
            // tile (epilogue 1 overwrites them with Y)
            const float4* av = (const float4*)A;
            for (int idx = tid; idx < 512; idx += 256) {
                int r = idx >> 2, seg = idx & 3;
                if (seg < 2) {
                    int n = m0 + r;
                    float4 f = make_float4(0.f, 0.f, 0.f, 0.f);
                    if (n < N) f = av[(size_t)n * 2 + seg];
                    uint32_t h, l;
                    split2(f.x, f.y, h, l);
                    sAh[r * PT + 2 * seg] = h;     sAl[r * PT + 2 * seg] = l;
                    split2(f.z, f.w, h, l);
                    sAh[r * PT + 2 * seg + 1] = h; sAl[r * PT + 2 * seg + 1] = l;
                } else {
                    sAh[r * PT + 2 * seg] = 0u;     sAl[r * PT + 2 * seg] = 0u;
                    sAh[r * PT + 2 * seg + 1] = 0u; sAl[r * PT + 2 * seg + 1] = 0u;
                }
            }
        }
        __syncthreads();

        // ---- GEMM1: D1 = A @ W1 (3-term) ----
#pragma unroll
        for (int mt = 0; mt < 2; mt++)
#pragma unroll
            for (int nt = 0; nt < 8; nt++)
#pragma unroll
                for (int j = 0; j < 4; j++) acc[mt][nt][j] = 0.f;

        gemm3(sAh, sAl, sW1h, sW1l, nks1, r0, n0, g, t, acc);
        __syncthreads();

        // ---- epilogue 1: Y = relu(D1 + b1) -> bf16 hi/lo into A buffers ----
#pragma unroll
        for (int mt = 0; mt < 2; mt++) {
            int r = r0 + mt * 16 + g;
#pragma unroll
            for (int nt = 0; nt < 8; nt++) {
                int c0 = n0 + nt * 8 + 2 * t;
                int kp = (c0 >> 1);
                float y0 = fmaxf(acc[mt][nt][0] + sb1[c0], 0.f);
                float y1 = fmaxf(acc[mt][nt][1] + sb1[c0 + 1], 0.f);
                float y2 = fmaxf(acc[mt][nt][2] + sb1[c0], 0.f);
                float y3 = fmaxf(acc[mt][nt][3] + sb1[c0 + 1], 0.f);
                uint32_t h, l;
                split2(y0, y1, h, l);
                sAh[r * PT + kp] = h; sAl[r * PT + kp] = l;
                split2(y2, y3, h, l);
                sAh[(r + 8) * PT + kp] = h; sAl[(r + 8) * PT + kp] = l;
            }
        }
        __syncthreads();

        // ---- GEMM2: D2 = Y @ W2 (3-term) ----
#pragma unroll
        for (int mt = 0; mt < 2; mt++)
#pragma unroll
            for (int nt = 0; nt < 8; nt++)
#pragma unroll
                for (int j = 0; j < 4; j++) acc[mt][nt][j] = 0.f;

        gemm3(sAh, sAl, sW2h, sW2l, 8, r0, n0, g, t, acc);
        __syncthreads();

        // ---- epilogue 2: relu(D2 + b2) -> fp32 staging ----
#pragma unroll
        for (int mt = 0; mt < 2; mt++) {
            int r = r0 + mt * 16 + g;
#pragma unroll
            for (int nt = 0; nt < 8; nt++) {
                int c0 = n0 + nt * 8 + 2 * t;
                sStage[r * PST + c0]           = fmaxf(acc[mt][nt][0] + sb2[c0], 0.f);
                sStage[r * PST + c0 + 1]       = fmaxf(acc[mt][nt][1] + sb2[c0 + 1], 0.f);
                sStage[(r + 8) * PST + c0]     = fmaxf(acc[mt][nt][2] + sb2[c0], 0.f);
                sStage[(r + 8) * PST + c0 + 1] = fmaxf(acc[mt][nt][3] + sb2[c0 + 1], 0.f);
            }
        }
        __syncthreads();

        // ---- coalesced store to gmem (skipped for conv3: no consumer) ----
        if (out != nullptr) {
            for (int idx = tid; idx < 4096; idx += 256) {
                int r = idx >> 5, q = idx & 31;
                int n = m0 + r;
                if (n < N)
                    *(float4*)&out[(size_t)n * HID + (q << 2)] =
                        *(const float4*)&sStage[r * PST + (q << 2)];
            }
        }

        // ---- fused global_add_pool: per-graph column sums from staging ----
        if (tid < 128) {
            int c = tid;
            float pa = 0.f;
            int gcur = sBatch[0];
            for (int r = 0; r < 128; r++) {
                int gb = sBatch[r];
                if (gb < 0) break;
                if (gb != gcur) {
                    atomicAdd(&pooled[(size_t)gcur * 384 + c], pa);
                    pa = 0.f;
                    gcur = gb;
                }
                pa += sStage[r * PST + c];
            }
            if (gcur >= 0) atomicAdd(&pooled[(size_t)gcur * 384 + c], pa);
        }

        // ---- steal next tile ----
        if (tid == 0) s_tile = gridDim.x + atomicAdd(&d_ctr[cid], 1);
        __syncthreads();  // also protects A/stage buffers
        tile = s_tile;
    }
}

// ---------------- classifier ---------------------------------------------------
__global__ void k_smallmm(const float* __restrict__ in, int K,
                          const float* __restrict__ w, const float* __restrict__ b,
                          int useCnt, float* __restrict__ out) {
    __shared__ float sp[8 * 384];
    int g0 = blockIdx.x * 8;
    int tid = threadIdx.x;  // 128
    for (int i = tid; i < 8 * K; i += 128) sp[i] = in[(size_t)g0 * K + i];
    __syncthreads();
    int c = tid;
    float acc[8] = {0.f, 0.f, 0.f, 0.f, 0.f, 0.f, 0.f, 0.f};
    for (int k = 0; k < K; k++) {
        float wv = w[k * HID + c];
#pragma unroll
        for (int j = 0; j < 8; j++) acc[j] += sp[j * K + k] * wv;
    }
    float bv = b[c];
#pragma unroll
    for (int j = 0; j < 8; j++) {
        int g = g0 + j;
        float scale = useCnt ? (float)(d_gstart[g + 1] - d_gstart[g]) : 1.f;
        out[(size_t)g * HID + c] = acc[j] + scale * bv;
    }
}

__global__ void k_bn() {
    __shared__ double ss[256], sq[256];
    int col = blockIdx.x, tid = threadIdx.x;
    double s = 0.0, q = 0.0;
    for (int r = tid; r < G_N; r += 256) {
        double v = (double)d_zc[(size_t)r * HID + col];
        s += v; q += v * v;
    }
    ss[tid] = s; sq[tid] = q;
    __syncthreads();
    for (int off = 128; off; off >>= 1) {
        if (tid < off) { ss[tid] += ss[tid + off]; sq[tid] += sq[tid + off]; }
        __syncthreads();
    }
    if (tid == 0) {
        double mu = ss[0] / G_N;
        double var = sq[0] / G_N - mu * mu;
        d_mu[col] = (float)mu;
        d_rstd[col] = (float)(1.0 / sqrt(var + 1e-5));
    }
}

__global__ void k_final(const float* __restrict__ bn_g, const float* __restrict__ bn_b,
                        const float* __restrict__ c2_w, const float* __restrict__ c2_b,
                        float* __restrict__ out) {
    __shared__ float r0s[128], r1s[128];
    int g = blockIdx.x, c = threadIdx.x;
    float z = (d_zc[(size_t)g * HID + c] - d_mu[c]) * d_rstd[c] * bn_g[c] + bn_b[c];
    z = fmaxf(z, 0.f);
    r0s[c] = z * c2_w[c * 2 + 0];
    r1s[c] = z * c2_w[c * 2 + 1];
    __syncthreads();
    for (int off = 64; off; off >>= 1) {
        if (c < off) { r0s[c] += r0s[c + off]; r1s[c] += r1s[c + off]; }
        __syncthreads();
    }
    if (c == 0) {
        out[g * 2 + 0] = r0s[0] + c2_b[0];
        out[g * 2 + 1] = r1s[0] + c2_b[1];
    }
}

// ---------------- host orchestration ------------------------------------------
extern "C" void kernel_launch(void* const* d_in, const int* in_sizes, int n_in,
                              void* d_out, int out_size) {
    const float* x     = (const float*)d_in[0];
    const int*   ei    = (const int*)d_in[1];
    const int*   batch = (const int*)d_in[3];
    const float* g1_w1 = (const float*)d_in[4];
    const float* g1_b1 = (const float*)d_in[5];
    const float* g1_w2 = (const float*)d_in[6];
    const float* g1_b2 = (const float*)d_in[7];
    const float* g2_w1 = (const float*)d_in[8];
    const float* g2_b1 = (const float*)d_in[9];
    const float* g2_w2 = (const float*)d_in[10];
    const float* g2_b2 = (const float*)d_in[11];
    const float* g3_w1 = (const float*)d_in[12];
    const float* g3_b1 = (const float*)d_in[13];
    const float* g3_w2 = (const float*)d_in[14];
    const float* g3_b2 = (const float*)d_in[15];
    const float* jk_w  = (const float*)d_in[16];
    const float* jk_b  = (const float*)d_in[17];
    const float* c1_w  = (const float*)d_in[18];
    const float* c1_b  = (const float*)d_in[19];
    const float* bn_g  = (const float*)d_in[20];
    const float* bn_b  = (const float*)d_in[21];
    const float* c2_w  = (const float*)d_in[22];
    const float* c2_b  = (const float*)d_in[23];
    float* out = (float*)d_out;

    int N = in_sizes[0] / 7;
    int E = in_sizes[1] / 2;
    const int* src = ei;
    const int* dst = ei + E;

    cudaFuncSetAttribute(k_mma_mlp, cudaFuncAttributeMaxDynamicSharedMemorySize, MMA_SMEM);

    // resolve true DEVICE addresses of __device__ globals (round-4 lesson)
    float *p_z8, *p_h1, *p_h2, *p_zbuf, *p_pooled, *p_grow, *p_zc;
    cudaGetSymbolAddress((void**)&p_z8,     d_z8);
    cudaGetSymbolAddress((void**)&p_h1,     d_h1);
    cudaGetSymbolAddress((void**)&p_h2,     d_h2);
    cudaGetSymbolAddress((void**)&p_zbuf,   d_zbuf);
    cudaGetSymbolAddress((void**)&p_pooled, d_pooled);
    cudaGetSymbolAddress((void**)&p_grow,   d_grow);
    cudaGetSymbolAddress((void**)&p_zc,     d_zc);

    int nb256 = (N + 255) / 256;
    int eb256 = (E + 255) / 256;

    // CSR build + graph boundaries (also resets steal counters + pooled)
    k_clear_gstart<<<nb256, 256>>>(batch, N);
    k_hist<<<eb256, 256>>>(dst, E);
    k_scan<<<1, 1024>>>(N, E);
    k_fill<<<eb256, 256>>>(src, dst, E);

    // conv1: 7-dim aggregation then bf16 3-term tensor-core fused MLP
    k_agg7<<<nb256, 256>>>(x, N);
    k_mma_mlp<<<148, 256, MMA_SMEM>>>(p_z8, 0, N, 1, 0,
                                      g1_w1, 7, g1_b1, g1_w2, g1_b2,
                                      p_h1, batch, p_pooled);
    // conv2
    k_agg128<<<(N + 7) / 8, 256>>>(p_h1, p_zbuf, N);
    k_mma_mlp<<<148, 256, MMA_SMEM>>>(p_zbuf, 1, N, 8, 1,
                                      g2_w1, 128, g2_b1, g2_w2, g2_b2,
                                      p_h2, batch, p_pooled + 128);
    // conv3 (h3 never stored — pooling consumes it from smem)
    k_agg128<<<(N + 7) / 8, 256>>>(p_h2, p_zbuf, N);
    k_mma_mlp<<<148, 256, MMA_SMEM>>>(p_zbuf, 1, N, 8, 2,
                                      g3_w1, 128, g3_b1, g3_w2, g3_b2,
                                      nullptr, batch, p_pooled + 256);

    // pool-first JK (pooled built in-epilogue): tiny GEMMs
    k_smallmm<<<G_N / 8, 128>>>(p_pooled, 384, jk_w, jk_b, 1, p_grow);
    k_smallmm<<<G_N / 8, 128>>>(p_grow, 128, c1_w, c1_b, 0, p_zc);

    // batch norm + classifier head
    k_bn<<<HID, 256>>>();
    k_final<<<G_N, 128>>>(bn_g, bn_b, c2_w, c2_b, out);
}

// round 17
// speedup vs baseline: 1.0239x; 1.0239x over previous
#include <cuda_runtime.h>
#include <cuda_bf16.h>
#include <cstdint>

#define G_N   2048
#define HID   128
#define NMAX  100000
#define EMAX  600000

// ---------------- scratch (static device globals; no allocations) -------------
static __device__ __align__(16) int   d_deg[NMAX];
static __device__ __align__(16) int   d_rowptr[NMAX + 1];
static __device__ __align__(16) int   d_woff[NMAX];
static __device__ __align__(16) int   d_csrsrc[EMAX];
static __device__ __align__(16) int   d_gstart[G_N + 1];
static __device__ __align__(16) int   d_ctr[4];
static __device__ __align__(16) float d_z8[(size_t)NMAX * 8];
static __device__ __align__(16) float d_h1[(size_t)NMAX * HID];
static __device__ __align__(16) float d_h2[(size_t)NMAX * HID];
static __device__ __align__(16) float d_zbuf[(size_t)NMAX * HID];
static __device__ __align__(16) float d_pooled[(size_t)G_N * 384];
static __device__ __align__(16) float d_grow[(size_t)G_N * HID];
static __device__ __align__(16) float d_zc[(size_t)G_N * HID];
static __device__ __align__(16) float d_mu[HID];
static __device__ __align__(16) float d_rstd[HID];

// ---------------- CSR build ---------------------------------------------------
// merged: clear degree + steal counters + pooled accumulator + graph starts
__global__ void k_clear_gstart(const int* __restrict__ batch, int N) {
    int n = blockIdx.x * blockDim.x + threadIdx.x;
    int nth = gridDim.x * blockDim.x;
    if (n < 4) d_ctr[n] = 0;
    for (int i = n; i < G_N * 384; i += nth) d_pooled[i] = 0.f;
    if (n >= N) return;
    d_deg[n] = 0;
    int b = batch[n];
    int bp = (n == 0) ? -1 : batch[n - 1];
    for (int g = bp + 1; g <= b; g++) d_gstart[g] = n;
    if (n == N - 1)
        for (int g = b + 1; g <= G_N; g++) d_gstart[g] = N;
}

__global__ void k_hist(const int* __restrict__ dst, int E) {
    int i = blockIdx.x * blockDim.x + threadIdx.x;
    if (i < E) atomicAdd(&d_deg[dst[i]], 1);
}

__global__ void k_scan(int N, int E) {
    __shared__ int part[1024];
    int tid = threadIdx.x;
    int chunk = (N + 1023) / 1024;
    int beg = tid * chunk;
    int end = min(beg + chunk, N);
    int s = 0;
    for (int i = beg; i < end; i++) s += d_deg[i];
    part[tid] = s;
    __syncthreads();
    for (int off = 1; off < 1024; off <<= 1) {
        int v = (tid >= off) ? part[tid - off] : 0;
        __syncthreads();
        part[tid] += v;
        __syncthreads();
    }
    int run = (tid == 0) ? 0 : part[tid - 1];
    for (int i = beg; i < end; i++) {
        d_rowptr[i] = run;
        d_woff[i] = run;
        run += d_deg[i];
    }
    if (tid == 1023) d_rowptr[N] = E;
}

__global__ void k_fill(const int* __restrict__ src, const int* __restrict__ dst, int E) {
    int i = blockIdx.x * blockDim.x + threadIdx.x;
    if (i < E) {
        int p = atomicAdd(&d_woff[dst[i]], 1);
        d_csrsrc[p] = src[i];
    }
}

// ---------------- aggregation (high-TLP standalone kernels) --------------------
__global__ void k_agg7(const float* __restrict__ x, int N) {
    int n = blockIdx.x * blockDim.x + threadIdx.x;
    if (n >= N) return;
    float a[8];
#pragma unroll
    for (int j = 0; j < 7; j++) a[j] = x[n * 7 + j];
    a[7] = 0.f;
    int b = d_rowptr[n], e = d_rowptr[n + 1];
    for (int i = b; i < e; i++) {
        int s = d_csrsrc[i];
#pragma unroll
        for (int j = 0; j < 7; j++) a[j] += x[s * 7 + j];
    }
#pragma unroll
    for (int j = 0; j < 8; j++) d_z8[(size_t)n * 8 + j] = a[j];
}

__global__ void k_agg128(const float* __restrict__ h, float* __restrict__ z, int N) {
    int w = (blockIdx.x * blockDim.x + threadIdx.x) >> 5;
    int lane = threadIdx.x & 31;
    if (w >= N) return;
    const float4* hv = (const float4*)h;
    float4 acc = hv[(size_t)w * 32 + lane];
    int b = d_rowptr[w], e = d_rowptr[w + 1];
    for (int i = b; i < e; i++) {
        int s = d_csrsrc[i];
        float4 v = hv[(size_t)s * 32 + lane];
        acc.x += v.x; acc.y += v.y; acc.z += v.z; acc.w += v.w;
    }
    ((float4*)z)[(size_t)w * 32 + lane] = acc;
}

// ============ bf16 3-term emulated-fp32 fused 2-layer MLP ======================
// out = relu( relu(A @ W1 + b1) @ W2 + b2 )
// pooled != nullptr: per-graph column sums accumulated from smem staging
// (global_add_pool fused — used ONLY for conv3, whose output has no other
// consumer, so both the 51MB store and the 51MB pool read vanish).
// Each fp32 operand x = hi(bf16) + lo(bf16); D = Ah@Wh + Ah@Wl + Al@Wh.
// mma.sync.m16n8k16 bf16; 256 threads (8 warps, 4x2), tile M=128 x N=128.
// Persistent CTAs + work-stealing tile scheduler (d_ctr reset each replay).

#define PT 68                                   // pitch in 32-bit words
#define TILE_W (128 * PT * 4)                   // 34816 bytes per bf16 tile
#define SM_AH  0
#define SM_AL  (TILE_W)
#define SM_W1H (2 * TILE_W)
#define SM_W1L (3 * TILE_W)
#define SM_W2H (4 * TILE_W)
#define SM_W2L (5 * TILE_W)
#define MMA_SMEM (6 * TILE_W)                   // 208896 bytes
#define PST 132                                 // fp32 staging pitch (reuses AH+AL)

__device__ __forceinline__ void mma16(float* c, const uint32_t* a, const uint32_t* b) {
    asm volatile(
        "mma.sync.aligned.m16n8k16.row.col.f32.bf16.bf16.f32 "
        "{%0,%1,%2,%3}, {%4,%5,%6,%7}, {%8,%9}, {%0,%1,%2,%3};"
        : "+f"(c[0]), "+f"(c[1]), "+f"(c[2]), "+f"(c[3])
        : "r"(a[0]), "r"(a[1]), "r"(a[2]), "r"(a[3]), "r"(b[0]), "r"(b[1]));
}

__device__ __forceinline__ void split2(float x0, float x1, uint32_t& h, uint32_t& l) {
    __nv_bfloat16 h0 = __float2bfloat16_rn(x0);
    __nv_bfloat16 h1 = __float2bfloat16_rn(x1);
    float r0 = x0 - __bfloat162float(h0);
    float r1 = x1 - __bfloat162float(h1);
    __nv_bfloat16 l0 = __float2bfloat16_rn(r0);
    __nv_bfloat16 l1 = __float2bfloat16_rn(r1);
    h = (uint32_t)__bfloat16_as_ushort(h0) | ((uint32_t)__bfloat16_as_ushort(h1) << 16);
    l = (uint32_t)__bfloat16_as_ushort(l0) | ((uint32_t)__bfloat16_as_ushort(l1) << 16);
}

__device__ __forceinline__ void gemm3(const uint32_t* sAh, const uint32_t* sAl,
                                      const uint32_t* sWh, const uint32_t* sWl,
                                      int nks, int r0, int n0, int g, int t,
                                      float acc[2][8][4]) {
    for (int ks = 0; ks < nks; ks++) {
        int kp0 = ks * 8;
        uint32_t ah[2][4], al[2][4];
#pragma unroll
        for (int mt = 0; mt < 2; mt++) {
            int rb = (r0 + mt * 16 + g) * PT + kp0 + t;
            ah[mt][0] = sAh[rb];              al[mt][0] = sAl[rb];
            ah[mt][1] = sAh[rb + 8 * PT];     al[mt][1] = sAl[rb + 8 * PT];
            ah[mt][2] = sAh[rb + 4];          al[mt][2] = sAl[rb + 4];
            ah[mt][3] = sAh[rb + 8 * PT + 4]; al[mt][3] = sAl[rb + 8 * PT + 4];
        }
#pragma unroll
        for (int nt = 0; nt < 8; nt++) {
            int wb = (n0 + nt * 8 + g) * PT + kp0 + t;
            uint32_t bh[2] = { sWh[wb], sWh[wb + 4] };
            uint32_t bl[2] = { sWl[wb], sWl[wb + 4] };
#pragma unroll
            for (int mt = 0; mt < 2; mt++) {
                mma16(acc[mt][nt], ah[mt], bh);
                mma16(acc[mt][nt], ah[mt], bl);
                mma16(acc[mt][nt], al[mt], bh);
            }
        }
    }
}

// mode 0: A = d_z8 [N,8] (7 real cols; kpairs 4..7 zeroed each tile), nks1 = 1
// mode 1: A = zbuf [N,128] float4-aligned, nks1 = 8
__global__ __launch_bounds__(256, 1)
void k_mma_mlp(const float* __restrict__ A, int mode, int N, int nks1, int cid,
               const float* __restrict__ W1, int kw1,
               const float* __restrict__ b1,
               const float* __restrict__ W2,
               const float* __restrict__ b2,
               float* __restrict__ out,
               const int* __restrict__ batch,
               float* __restrict__ pooled) {
    extern __shared__ char dsm[];
    uint32_t* sAh  = (uint32_t*)(dsm + SM_AH);
    uint32_t* sAl  = (uint32_t*)(dsm + SM_AL);
    uint32_t* sW1h = (uint32_t*)(dsm + SM_W1H);
    uint32_t* sW1l = (uint32_t*)(dsm + SM_W1L);
    uint32_t* sW2h = (uint32_t*)(dsm + SM_W2H);
    uint32_t* sW2l = (uint32_t*)(dsm + SM_W2L);
    float*    sStage = (float*)(dsm + SM_AH);   // fp32 staging reuses AH+AL
    __shared__ float sb1[128], sb2[128];
    __shared__ int sBatch[128];
    __shared__ int s_tile;

    int tid = threadIdx.x;
    int wid = tid >> 5, lane = tid & 31;
    int g = lane >> 2, t = lane & 3;
    int wr = wid & 3, wc = wid >> 2;
    int r0 = wr * 32;
    int n0 = wc * 64;

    if (tid < 128) { sb1[tid] = b1[tid]; sb2[tid] = b2[tid]; }

    // W1 -> transposed [n][kpair] hi/lo, zero-pad k >= kw1
    int kpw1 = nks1 * 8;
    for (int idx = tid; idx < 128 * kpw1; idx += 256) {
        int n = idx & 127, p = idx >> 7;
        int k0 = 2 * p, k1 = 2 * p + 1;
        float w0 = (k0 < kw1) ? W1[k0 * HID + n] : 0.f;
        float w1 = (k1 < kw1) ? W1[k1 * HID + n] : 0.f;
        uint32_t h, l;
        split2(w0, w1, h, l);
        sW1h[n * PT + p] = h;
        sW1l[n * PT + p] = l;
    }
    // W2 -> transposed [n][kpair] hi/lo
    for (int idx = tid; idx < 8192; idx += 256) {
        int n = idx & 127, p = idx >> 7;
        float w0 = W2[(2 * p) * HID + n];
        float w1 = W2[(2 * p + 1) * HID + n];
        uint32_t h, l;
        split2(w0, w1, h, l);
        sW2h[n * PT + p] = h;
        sW2l[n * PT + p] = l;
    }
    __syncthreads();

    int ntiles = (N + 127) >> 7;
    float acc[2][8][4];

    int tile = blockIdx.x;
    while (tile < ntiles) {
        int m0 = tile << 7;

        // ---- A-tile load -> bf16 hi/lo kpair words (+ batch slice) ----
        if (pooled != nullptr && tid < 128) {
            int n = m0 + tid;
            sBatch[tid] = (n < N) ? batch[n] : -1;
        }
        if (mode == 1) {
            const float4* av = (const float4*)A;
            for (int idx = tid; idx < 4096; idx += 256) {
                int r = idx >> 5, seg = idx & 31;
                int n = m0 + r;
                float4 f = make_float4(0.f, 0.f, 0.f, 0.f);
                if (n < N) f = av[(size_t)n * 32 + seg];
                uint32_t h, l;
                split2(f.x, f.y, h, l);
                sAh[r * PT + 2 * seg] = h;     sAl[r * PT + 2 * seg] = l;
                split2(f.z, f.w, h, l);
                sAh[r * PT + 2 * seg + 1] = h; sAl[r * PT + 2 * seg + 1] = l;
            }
        } else {
            // d_z8: 2 float4/row (kpairs 0..3); kpairs 4..7 MUST be zeroed each
            // tile (epilogue 1 overwrites them with Y)
            const float4* av = (const float4*)A;
            for (int idx = tid; idx < 512; idx += 256) {
                int r = idx >> 2, seg = idx & 3;
                if (seg < 2) {
                    int n = m0 + r;
                    float4 f = make_float4(0.f, 0.f, 0.f, 0.f);
                    if (n < N) f = av[(size_t)n * 2 + seg];
                    uint32_t h, l;
                    split2(f.x, f.y, h, l);
                    sAh[r * PT + 2 * seg] = h;     sAl[r * PT + 2 * seg] = l;
                    split2(f.z, f.w, h, l);
                    sAh[r * PT + 2 * seg + 1] = h; sAl[r * PT + 2 * seg + 1] = l;
                } else {
                    sAh[r * PT + 2 * seg] = 0u;     sAl[r * PT + 2 * seg] = 0u;
                    sAh[r * PT + 2 * seg + 1] = 0u; sAl[r * PT + 2 * seg + 1] = 0u;
                }
            }
        }
        __syncthreads();

        // ---- GEMM1: D1 = A @ W1 (3-term) ----
#pragma unroll
        for (int mt = 0; mt < 2; mt++)
#pragma unroll
            for (int nt = 0; nt < 8; nt++)
#pragma unroll
                for (int j = 0; j < 4; j++) acc[mt][nt][j] = 0.f;

        gemm3(sAh, sAl, sW1h, sW1l, nks1, r0, n0, g, t, acc);
        __syncthreads();

        // ---- epilogue 1: Y = relu(D1 + b1) -> bf16 hi/lo into A buffers ----
#pragma unroll
        for (int mt = 0; mt < 2; mt++) {
            int r = r0 + mt * 16 + g;
#pragma unroll
            for (int nt = 0; nt < 8; nt++) {
                int c0 = n0 + nt * 8 + 2 * t;
                int kp = (c0 >> 1);
                float y0 = fmaxf(acc[mt][nt][0] + sb1[c0], 0.f);
                float y1 = fmaxf(acc[mt][nt][1] + sb1[c0 + 1], 0.f);
                float y2 = fmaxf(acc[mt][nt][2] + sb1[c0], 0.f);
                float y3 = fmaxf(acc[mt][nt][3] + sb1[c0 + 1], 0.f);
                uint32_t h, l;
                split2(y0, y1, h, l);
                sAh[r * PT + kp] = h; sAl[r * PT + kp] = l;
                split2(y2, y3, h, l);
                sAh[(r + 8) * PT + kp] = h; sAl[(r + 8) * PT + kp] = l;
            }
        }
        __syncthreads();

        // ---- GEMM2: D2 = Y @ W2 (3-term) ----
#pragma unroll
        for (int mt = 0; mt < 2; mt++)
#pragma unroll
            for (int nt = 0; nt < 8; nt++)
#pragma unroll
                for (int j = 0; j < 4; j++) acc[mt][nt][j] = 0.f;

        gemm3(sAh, sAl, sW2h, sW2l, 8, r0, n0, g, t, acc);
        __syncthreads();

        // ---- epilogue 2: relu(D2 + b2) -> fp32 staging ----
#pragma unroll
        for (int mt = 0; mt < 2; mt++) {
            int r = r0 + mt * 16 + g;
#pragma unroll
            for (int nt = 0; nt < 8; nt++) {
                int c0 = n0 + nt * 8 + 2 * t;
                sStage[r * PST + c0]           = fmaxf(acc[mt][nt][0] + sb2[c0], 0.f);
                sStage[r * PST + c0 + 1]       = fmaxf(acc[mt][nt][1] + sb2[c0 + 1], 0.f);
                sStage[(r + 8) * PST + c0]     = fmaxf(acc[mt][nt][2] + sb2[c0], 0.f);
                sStage[(r + 8) * PST + c0 + 1] = fmaxf(acc[mt][nt][3] + sb2[c0 + 1], 0.f);
            }
        }
        __syncthreads();

        // ---- coalesced store to gmem (conv1/conv2) ----
        if (out != nullptr) {
            for (int idx = tid; idx < 4096; idx += 256) {
                int r = idx >> 5, q = idx & 31;
                int n = m0 + r;
                if (n < N)
                    *(float4*)&out[(size_t)n * HID + (q << 2)] =
                        *(const float4*)&sStage[r * PST + (q << 2)];
            }
        }

        // ---- fused global_add_pool (conv3 only): all 256 threads, 64 rows each
        if (pooled != nullptr) {
            int c = tid & 127;
            int rbeg = (tid >> 7) * 64, rend = rbeg + 64;
            float pa = 0.f;
            int gcur = sBatch[rbeg];
            for (int r = rbeg; r < rend; r++) {
                int gb = sBatch[r];
                if (gb < 0) break;
                if (gb != gcur) {
                    atomicAdd(&pooled[(size_t)gcur * 384 + c], pa);
                    pa = 0.f;
                    gcur = gb;
                }
                pa += sStage[r * PST + c];
            }
            if (gcur >= 0) atomicAdd(&pooled[(size_t)gcur * 384 + c], pa);
        }

        // ---- steal next tile ----
        if (tid == 0) s_tile = gridDim.x + atomicAdd(&d_ctr[cid], 1);
        __syncthreads();  // also protects A/stage buffers
        tile = s_tile;
    }
}

// ---------------- pooling (h1, h2 from gmem; h3 fused in conv3) ----------------
// 256 threads: thread = (array a in {0,1}, column c)
__global__ void k_pool(const float* __restrict__ h1, const float* __restrict__ h2) {
    int gph = blockIdx.x;
    int tid = threadIdx.x;           // 0..255
    int a = tid >> 7, c = tid & 127;
    const float* h = (a == 0) ? h1 : h2;
    int s = d_gstart[gph], e = d_gstart[gph + 1];
    float acc = 0.f;
    for (int r = s; r < e; r++) acc += h[(size_t)r * HID + c];
    d_pooled[(size_t)gph * 384 + a * 128 + c] = acc;
}

// ---------------- classifier ---------------------------------------------------
__global__ void k_smallmm(const float* __restrict__ in, int K,
                          const float* __restrict__ w, const float* __restrict__ b,
                          int useCnt, float* __restrict__ out) {
    __shared__ float sp[8 * 384];
    int g0 = blockIdx.x * 8;
    int tid = threadIdx.x;  // 128
    for (int i = tid; i < 8 * K; i += 128) sp[i] = in[(size_t)g0 * K + i];
    __syncthreads();
    int c = tid;
    float acc[8] = {0.f, 0.f, 0.f, 0.f, 0.f, 0.f, 0.f, 0.f};
    for (int k = 0; k < K; k++) {
        float wv = w[k * HID + c];
#pragma unroll
        for (int j = 0; j < 8; j++) acc[j] += sp[j * K + k] * wv;
    }
    float bv = b[c];
#pragma unroll
    for (int j = 0; j < 8; j++) {
        int g = g0 + j;
        float scale = useCnt ? (float)(d_gstart[g + 1] - d_gstart[g]) : 1.f;
        out[(size_t)g * HID + c] = acc[j] + scale * bv;
    }
}

__global__ void k_bn() {
    __shared__ double ss[256], sq[256];
    int col = blockIdx.x, tid = threadIdx.x;
    double s = 0.0, q = 0.0;
    for (int r = tid; r < G_N; r += 256) {
        double v = (double)d_zc[(size_t)r * HID + col];
        s += v; q += v * v;
    }
    ss[tid] = s; sq[tid] = q;
    __syncthreads();
    for (int off = 128; off; off >>= 1) {
        if (tid < off) { ss[tid] += ss[tid + off]; sq[tid] += sq[tid + off]; }
        __syncthreads();
    }
    if (tid == 0) {
        double mu = ss[0] / G_N;
        double var = sq[0] / G_N - mu * mu;
        d_mu[col] = (float)mu;
        d_rstd[col] = (float)(1.0 / sqrt(var + 1e-5));
    }
}

__global__ void k_final(const float* __restrict__ bn_g, const float* __restrict__ bn_b,
                        const float* __restrict__ c2_w, const float* __restrict__ c2_b,
                        float* __restrict__ out) {
    __shared__ float r0s[128], r1s[128];
    int g = blockIdx.x, c = threadIdx.x;
    float z = (d_zc[(size_t)g * HID + c] - d_mu[c]) * d_rstd[c] * bn_g[c] + bn_b[c];
    z = fmaxf(z, 0.f);
    r0s[c] = z * c2_w[c * 2 + 0];
    r1s[c] = z * c2_w[c * 2 + 1];
    __syncthreads();
    for (int off = 64; off; off >>= 1) {
        if (c < off) { r0s[c] += r0s[c + off]; r1s[c] += r1s[c + off]; }
        __syncthreads();
    }
    if (c == 0) {
        out[g * 2 + 0] = r0s[0] + c2_b[0];
        out[g * 2 + 1] = r1s[0] + c2_b[1];
    }
}

// ---------------- host orchestration ------------------------------------------
extern "C" void kernel_launch(void* const* d_in, const int* in_sizes, int n_in,
                              void* d_out, int out_size) {
    const float* x     = (const float*)d_in[0];
    const int*   ei    = (const int*)d_in[1];
    const int*   batch = (const int*)d_in[3];
    const float* g1_w1 = (const float*)d_in[4];
    const float* g1_b1 = (const float*)d_in[5];
    const float* g1_w2 = (const float*)d_in[6];
    const float* g1_b2 = (const float*)d_in[7];
    const float* g2_w1 = (const float*)d_in[8];
    const float* g2_b1 = (const float*)d_in[9];
    const float* g2_w2 = (const float*)d_in[10];
    const float* g2_b2 = (const float*)d_in[11];
    const float* g3_w1 = (const float*)d_in[12];
    const float* g3_b1 = (const float*)d_in[13];
    const float* g3_w2 = (const float*)d_in[14];
    const float* g3_b2 = (const float*)d_in[15];
    const float* jk_w  = (const float*)d_in[16];
    const float* jk_b  = (const float*)d_in[17];
    const float* c1_w  = (const float*)d_in[18];
    const float* c1_b  = (const float*)d_in[19];
    const float* bn_g  = (const float*)d_in[20];
    const float* bn_b  = (const float*)d_in[21];
    const float* c2_w  = (const float*)d_in[22];
    const float* c2_b  = (const float*)d_in[23];
    float* out = (float*)d_out;

    int N = in_sizes[0] / 7;
    int E = in_sizes[1] / 2;
    const int* src = ei;
    const int* dst = ei + E;

    cudaFuncSetAttribute(k_mma_mlp, cudaFuncAttributeMaxDynamicSharedMemorySize, MMA_SMEM);

    // resolve true DEVICE addresses of __device__ globals (round-4 lesson)
    float *p_z8, *p_h1, *p_h2, *p_zbuf, *p_pooled, *p_grow, *p_zc;
    cudaGetSymbolAddress((void**)&p_z8,     d_z8);
    cudaGetSymbolAddress((void**)&p_h1,     d_h1);
    cudaGetSymbolAddress((void**)&p_h2,     d_h2);
    cudaGetSymbolAddress((void**)&p_zbuf,   d_zbuf);
    cudaGetSymbolAddress((void**)&p_pooled, d_pooled);
    cudaGetSymbolAddress((void**)&p_grow,   d_grow);
    cudaGetSymbolAddress((void**)&p_zc,     d_zc);

    int nb256 = (N + 255) / 256;
    int eb256 = (E + 255) / 256;

    // CSR build + graph boundaries (also resets steal counters + pooled)
    k_clear_gstart<<<nb256, 256>>>(batch, N);
    k_hist<<<eb256, 256>>>(dst, E);
    k_scan<<<1, 1024>>>(N, E);
    k_fill<<<eb256, 256>>>(src, dst, E);

    // conv1: 7-dim aggregation then bf16 3-term tensor-core fused MLP
    k_agg7<<<nb256, 256>>>(x, N);
    k_mma_mlp<<<148, 256, MMA_SMEM>>>(p_z8, 0, N, 1, 0,
                                      g1_w1, 7, g1_b1, g1_w2, g1_b2,
                                      p_h1, nullptr, nullptr);
    // conv2
    k_agg128<<<(N + 7) / 8, 256>>>(p_h1, p_zbuf, N);
    k_mma_mlp<<<148, 256, MMA_SMEM>>>(p_zbuf, 1, N, 8, 1,
                                      g2_w1, 128, g2_b1, g2_w2, g2_b2,
                                      p_h2, nullptr, nullptr);
    // conv3: h3 never stored — pooling fused into the epilogue
    k_agg128<<<(N + 7) / 8, 256>>>(p_h2, p_zbuf, N);
    k_mma_mlp<<<148, 256, MMA_SMEM>>>(p_zbuf, 1, N, 8, 2,
                                      g3_w1, 128, g3_b1, g3_w2, g3_b2,
                                      nullptr, batch, p_pooled + 256);

    // pool h1/h2 from gmem (h3 part already accumulated), then tiny GEMMs
    k_pool<<<G_N, 256>>>(p_h1, p_h2);
    k_smallmm<<<G_N / 8, 128>>>(p_pooled, 384, jk_w, jk_b, 1, p_grow);
    k_smallmm<<<G_N / 8, 128>>>(p_grow, 128, c1_w, c1_b, 0, p_zc);

    // batch norm + classifier head
    k_bn<<<HID, 256>>>();
    k_final<<<G_N, 128>>>(bn_g, bn_b, c2_w, c2_b, out);
}